// round 5
// baseline (speedup 1.0000x reference)
#include <cuda_runtime.h>
#include <cuda_bf16.h>
#include <cstdint>
#include <cstddef>

#define B_     128
#define C_     3
#define IMG_   224
#define P_     16
#define HP_    14
#define NP_    196
#define S_     197
#define D_     384
#define HEADS_ 6
#define HD_    64
#define DEPTH_ 12
#define HID_   1536
#define NCLS_  100
#define PD_    768
#define T_     (B_*S_)    // 25216
#define BT_    (B_*NP_)   // 25088
#define TRID_  (3*D_)     // 1152

typedef unsigned long long ull;

// ===================== helpers =====================
__device__ __forceinline__ uint32_t smem_u32(const void* p) {
    uint32_t a;
    asm("{ .reg .u64 t; cvta.to.shared.u64 t, %1; cvt.u32.u64 %0, t; }" : "=r"(a) : "l"(p));
    return a;
}
__device__ __forceinline__ void cp16(uint32_t saddr, const void* g) {
    asm volatile("cp.async.cg.shared.global [%0], [%1], 16;" :: "r"(saddr), "l"(g));
}
#define CP_COMMIT() asm volatile("cp.async.commit_group;" ::: "memory")
#define CP_WAIT(n)  asm volatile("cp.async.wait_group %0;" :: "n"(n) : "memory")

__device__ __forceinline__ void ldsm4(uint32_t& r0, uint32_t& r1, uint32_t& r2, uint32_t& r3,
                                      uint32_t a) {
    asm volatile("ldmatrix.sync.aligned.m8n8.x4.shared.b16 {%0,%1,%2,%3}, [%4];"
                 : "=r"(r0), "=r"(r1), "=r"(r2), "=r"(r3) : "r"(a));
}
__device__ __forceinline__ void mma16816(float* c, uint32_t a0, uint32_t a1, uint32_t a2,
                                         uint32_t a3, uint32_t b0, uint32_t b1) {
    asm volatile("mma.sync.aligned.m16n8k16.row.col.f32.bf16.bf16.f32 "
                 "{%0,%1,%2,%3}, {%4,%5,%6,%7}, {%8,%9}, {%0,%1,%2,%3};"
                 : "+f"(c[0]), "+f"(c[1]), "+f"(c[2]), "+f"(c[3])
                 : "r"(a0), "r"(a1), "r"(a2), "r"(a3), "r"(b0), "r"(b1));
}

// f32x2 helpers for attention
__device__ __forceinline__ void ffma2(ull& acc, ull a, ull b) {
    asm("fma.rn.f32x2 %0, %1, %2, %0;" : "+l"(acc) : "l"(a), "l"(b));
}
__device__ __forceinline__ ull packdup(float a) {
    ull r; asm("mov.b64 %0, {%1, %1};" : "=l"(r) : "f"(a)); return r;
}
__device__ __forceinline__ ull pack2(float lo, float hi) {
    ull r; asm("mov.b64 %0, {%1, %2};" : "=l"(r) : "f"(lo), "f"(hi)); return r;
}
__device__ __forceinline__ void unpack2(ull v, float& lo, float& hi) {
    asm("mov.b64 {%0, %1}, %2;" : "=f"(lo), "=f"(hi) : "l"(v));
}
__device__ __forceinline__ void mul2(ull& v, ull s) {
    asm("mul.rn.f32x2 %0, %1, %2;" : "=l"(v) : "l"(v), "l"(s));
}
__device__ __forceinline__ void split_bf(float x, __nv_bfloat16& hi, __nv_bfloat16& lo) {
    hi = __float2bfloat16(x);
    lo = __float2bfloat16(x - __bfloat162float(hi));
}

// ===================== scratch =====================
__device__ float g_h[(size_t)T_*D_];
__device__ float g_tok[(size_t)BT_*D_];
__device__ float g_qkv[(size_t)T_*TRID_];
__device__ float g_cls[B_*D_];
__device__ __nv_bfloat16 g_x2[(size_t)T_*3*D_];
__device__ __nv_bfloat16 g_ctx2[(size_t)T_*3*D_];
__device__ __nv_bfloat16 g_hid2[(size_t)T_*3*HID_];
__device__ __nv_bfloat16 g_p2[(size_t)BT_*3*PD_];
__device__ __nv_bfloat16 g_pw2[(size_t)D_*3*PD_];
__device__ __nv_bfloat16 g_qkvw2[(size_t)DEPTH_*TRID_*3*D_];
__device__ __nv_bfloat16 g_outw2[(size_t)DEPTH_*D_*3*D_];
__device__ __nv_bfloat16 g_fc1w2[(size_t)DEPTH_*HID_*3*D_];
__device__ __nv_bfloat16 g_fc2w2[(size_t)DEPTH_*D_*3*HID_];

// ===================== weight split =====================
__global__ void wsplit_k(const float* __restrict__ src, __nv_bfloat16* __restrict__ dst,
                         int R, int K) {
    size_t idx = (size_t)blockIdx.x * blockDim.x + threadIdx.x;
    if (idx >= (size_t)R * K) return;
    int r = (int)(idx / K), k = (int)(idx - (size_t)r * K);
    __nv_bfloat16 hi, lo;
    split_bf(src[idx], hi, lo);
    size_t rb = (size_t)r * 3 * K;
    dst[rb + k] = hi;
    dst[rb + K + k] = lo;
    dst[rb + 2*K + k] = hi;
}

// ===================== patchify -> split =====================
__global__ void patchify_k(const float* __restrict__ x, __nv_bfloat16* __restrict__ out) {
    size_t idx = (size_t)blockIdx.x * blockDim.x + threadIdx.x;
    if (idx >= (size_t)BT_*PD_) return;
    int t = (int)(idx / PD_), j = (int)(idx - (size_t)t * PD_);
    int b = t / NP_, p = t - b*NP_;
    int ph = p / HP_, pw = p - ph*HP_;
    int c = j >> 8, r = (j >> 4) & 15, col = j & 15;
    float v = x[(((size_t)b*C_ + c)*IMG_ + ph*P_ + r)*IMG_ + pw*P_ + col];
    __nv_bfloat16 hi, lo;
    split_bf(v, hi, lo);
    size_t rb = (size_t)t * 3 * PD_;
    out[rb + j] = hi;
    out[rb + PD_ + j] = hi;
    out[rb + 2*PD_ + j] = lo;
}

// ===================== assemble =====================
__global__ void assemble_k(const float* __restrict__ tok, const float* __restrict__ cls,
                           const float* __restrict__ pos, float* __restrict__ h) {
    int idx = blockIdx.x * blockDim.x + threadIdx.x;
    if (idx >= T_*D_) return;
    int t = idx / D_, d = idx - t*D_;
    int b = t / S_, s = t - b*S_;
    float v = (s == 0) ? cls[d] : tok[(size_t)(b*NP_ + s - 1)*D_ + d];
    h[idx] = v + pos[s*D_ + d];
}

// ===================== layernorm =====================
template <int SPLIT>
__global__ void ln_k(const float* __restrict__ in, float* __restrict__ outf,
                     __nv_bfloat16* __restrict__ out2,
                     const float* __restrict__ g, const float* __restrict__ bta,
                     int rows, int instride) {
    int warp = (blockIdx.x * blockDim.x + threadIdx.x) >> 5;
    int lane = threadIdx.x & 31;
    if (warp >= rows) return;
    const float* row = in + (size_t)warp * instride;
    float v[12];
    float s = 0.f;
#pragma unroll
    for (int i = 0; i < 12; i++) { v[i] = row[lane + i*32]; s += v[i]; }
#pragma unroll
    for (int o = 16; o > 0; o >>= 1) s += __shfl_xor_sync(0xffffffffu, s, o);
    float mean = s * (1.f/384.f);
    float vs = 0.f;
#pragma unroll
    for (int i = 0; i < 12; i++) { float d = v[i] - mean; vs += d*d; }
#pragma unroll
    for (int o = 16; o > 0; o >>= 1) vs += __shfl_xor_sync(0xffffffffu, vs, o);
    float rstd = rsqrtf(vs * (1.f/384.f) + 1e-5f);
    if (SPLIT) {
        size_t rb = (size_t)warp * (3*D_);
#pragma unroll
        for (int i = 0; i < 12; i++) {
            int c = lane + i*32;
            float y = (v[i] - mean) * rstd * g[c] + bta[c];
            __nv_bfloat16 hi, lo;
            split_bf(y, hi, lo);
            out2[rb + c] = hi;
            out2[rb + D_ + c] = hi;
            out2[rb + 2*D_ + c] = lo;
        }
    } else {
        float* orow = outf + (size_t)warp * D_;
#pragma unroll
        for (int i = 0; i < 12; i++) {
            int c = lane + i*32;
            orow[c] = (v[i] - mean) * rstd * g[c] + bta[c];
        }
    }
}

// ===================== mma.sync bf16 GEMM, 4-stage pipeline =====================
// C[M,N] = A2[M,K2] @ W2[N,K2]^T (+bias)
// MODE 0: fp32 store. MODE 1: fp32 resid add. MODE 2: gelu -> split bf16 [hi,hi,lo].
// 4 warps (128 thr), warp tile 64x64, CTA 128x128, K-chunk 32, stages=4.
// SMEM stage: A 128x32 (8KB) + B 128x32 (8KB) = 16KB; 4 stages = 64KB.
#define GMM_SMEM 65536
#define STAGE_BYTES 16384
template <int MODE>
__global__ void __launch_bounds__(128, 2)
gemm_mma(const __nv_bfloat16* __restrict__ A, const __nv_bfloat16* __restrict__ W,
         const float* __restrict__ bias, const float* __restrict__ resid,
         void* __restrict__ Cout, int M, int N, int K2) {
    extern __shared__ char dsm[];
    uint32_t sbase = smem_u32(dsm);

    int tid = threadIdx.x;
    int wid = tid >> 5, lane = tid & 31;
    int wm = wid & 1, wn = wid >> 1;        // 2x2 warp grid, 64x64 tiles
    int m0 = blockIdx.y * 128, n0 = blockIdx.x * 128;

    // loader: 4 tasks/thread for A, 4 for B: task = tid + 128*i, r = task>>2, c = task&3
    uint32_t soA[4], soB[4];
    const __nv_bfloat16 *Ag[4], *Wg[4];
#pragma unroll
    for (int i = 0; i < 4; i++) {
        int task = tid + 128*i;
        int r = task >> 2, c = task & 3;
        uint32_t sw = (uint32_t)(c ^ ((r >> 1) & 3));
        soA[i] = r*64 + (sw << 4);
        soB[i] = 8192 + r*64 + (sw << 4);
        Ag[i] = A + (size_t)(m0 + r)*K2 + c*8;
        Wg[i] = W + (size_t)(n0 + r)*K2 + c*8;
    }

    float acc[4][8][4];
#pragma unroll
    for (int f = 0; f < 4; f++)
#pragma unroll
        for (int g = 0; g < 8; g++)
#pragma unroll
            for (int e = 0; e < 4; e++) acc[f][g][e] = 0.f;

    int nc = K2 >> 5;   // chunks of 32

    // prologue: stages 0..2
#pragma unroll
    for (int s = 0; s < 3; s++) {
        if (s < nc) {
            uint32_t st = sbase + (uint32_t)s * STAGE_BYTES;
#pragma unroll
            for (int i = 0; i < 4; i++) {
                cp16(st + soA[i], Ag[i] + (size_t)s*32);
                cp16(st + soB[i], Wg[i] + (size_t)s*32);
            }
        }
        CP_COMMIT();
    }

    for (int ch = 0; ch < nc; ch++) {
        CP_WAIT(2);
        __syncthreads();
        // issue stage ch+3 (buf (ch+3)&3 == (ch-1)&3, safe after barrier)
        {
            int nst = ch + 3;
            if (nst < nc) {
                uint32_t st = sbase + (uint32_t)(nst & 3) * STAGE_BYTES;
#pragma unroll
                for (int i = 0; i < 4; i++) {
                    cp16(st + soA[i], Ag[i] + (size_t)nst*32);
                    cp16(st + soB[i], Wg[i] + (size_t)nst*32);
                }
            }
            CP_COMMIT();
        }
        // compute chunk ch from buf ch&3
        uint32_t st = sbase + (uint32_t)(ch & 3) * STAGE_BYTES;
#pragma unroll
        for (int ks = 0; ks < 2; ks++) {
            uint32_t a[4][4];
#pragma unroll
            for (int f = 0; f < 4; f++) {
                int r = wm*64 + f*16 + (lane & 15);
                int kc = ks*2 + (lane >> 4);
                uint32_t addr = st + r*64 + (((uint32_t)(kc ^ ((r >> 1) & 3))) << 4);
                ldsm4(a[f][0], a[f][1], a[f][2], a[f][3], addr);
            }
            uint32_t b[4][4];
#pragma unroll
            for (int g2 = 0; g2 < 4; g2++) {
                int nr = wn*64 + g2*16 + ((lane >> 4) << 3) + (lane & 7);
                int kc = ks*2 + ((lane >> 3) & 1);
                uint32_t addr = st + 8192 + nr*64 + (((uint32_t)(kc ^ ((nr >> 1) & 3))) << 4);
                ldsm4(b[g2][0], b[g2][1], b[g2][2], b[g2][3], addr);
            }
#pragma unroll
            for (int f = 0; f < 4; f++)
#pragma unroll
                for (int g = 0; g < 8; g++)
                    mma16816(acc[f][g], a[f][0], a[f][1], a[f][2], a[f][3],
                             b[g >> 1][(g & 1)*2], b[g >> 1][(g & 1)*2 + 1]);
        }
    }

    // epilogue
#pragma unroll
    for (int f = 0; f < 4; f++) {
        int m = m0 + wm*64 + f*16 + (lane >> 2);
#pragma unroll
        for (int g = 0; g < 8; g++) {
            int n = n0 + wn*64 + g*8 + (lane & 3)*2;
            float bn0 = bias[n], bn1 = bias[n + 1];
            float v00 = acc[f][g][0] + bn0, v01 = acc[f][g][1] + bn1;
            float v10 = acc[f][g][2] + bn0, v11 = acc[f][g][3] + bn1;
            if (MODE == 1) {
                const float* r0p = resid + (size_t)m*N + n;
                const float* r1p = resid + (size_t)(m + 8)*N + n;
                v00 += r0p[0]; v01 += r0p[1];
                v10 += r1p[0]; v11 += r1p[1];
            }
            if (MODE == 2) {
                v00 = 0.5f * v00 * (1.f + erff(v00 * 0.70710678118654752f));
                v01 = 0.5f * v01 * (1.f + erff(v01 * 0.70710678118654752f));
                v10 = 0.5f * v10 * (1.f + erff(v10 * 0.70710678118654752f));
                v11 = 0.5f * v11 * (1.f + erff(v11 * 0.70710678118654752f));
                __nv_bfloat16* H = (__nv_bfloat16*)Cout;
                size_t rb0 = (size_t)m * (3*N), rb1 = (size_t)(m + 8) * (3*N);
                __nv_bfloat16 h0, l0, h1, l1;
                split_bf(v00, h0, l0); split_bf(v01, h1, l1);
                __nv_bfloat162 hh, llv;
                hh.x = h0; hh.y = h1; llv.x = l0; llv.y = l1;
                *(__nv_bfloat162*)(H + rb0 + n)       = hh;
                *(__nv_bfloat162*)(H + rb0 + N + n)   = hh;
                *(__nv_bfloat162*)(H + rb0 + 2*N + n) = llv;
                split_bf(v10, h0, l0); split_bf(v11, h1, l1);
                hh.x = h0; hh.y = h1; llv.x = l0; llv.y = l1;
                *(__nv_bfloat162*)(H + rb1 + n)       = hh;
                *(__nv_bfloat162*)(H + rb1 + N + n)   = hh;
                *(__nv_bfloat162*)(H + rb1 + 2*N + n) = llv;
            } else {
                float* Cf = (float*)Cout;
                *(float2*)(Cf + (size_t)m*N + n)       = make_float2(v00, v01);
                *(float2*)(Cf + (size_t)(m + 8)*N + n) = make_float2(v10, v11);
            }
        }
    }
}

// ===================== fp32 GEMM for head only =====================
__global__ void __launch_bounds__(256)
gemm32_k(const float* __restrict__ A, const float* __restrict__ W,
         float* __restrict__ C, int M, int N, int K) {
    __shared__ float As[8][132];
    __shared__ float Bs[8][132];
    int tid = threadIdx.x;
    int m0 = blockIdx.y * 128, n0 = blockIdx.x * 128;
    int ty = tid >> 4, tx = tid & 15;
    int lr = tid >> 1;
    int lk = (tid & 1) * 4;
    float acc[8][8];
#pragma unroll
    for (int i = 0; i < 8; i++)
#pragma unroll
        for (int j = 0; j < 8; j++) acc[i][j] = 0.f;
    bool av = (m0 + lr) < M;
    bool wv = (n0 + lr) < N;
    const float* Aptr = A + (size_t)(m0 + lr) * K + lk;
    const float* Wptr = W + (size_t)(n0 + lr) * K + lk;
    for (int k0 = 0; k0 < K; k0 += 8) {
        float4 va = av ? *(const float4*)(Aptr + k0) : make_float4(0.f,0.f,0.f,0.f);
        float4 vb = wv ? *(const float4*)(Wptr + k0) : make_float4(0.f,0.f,0.f,0.f);
        __syncthreads();
        As[lk+0][lr]=va.x; As[lk+1][lr]=va.y; As[lk+2][lr]=va.z; As[lk+3][lr]=va.w;
        Bs[lk+0][lr]=vb.x; Bs[lk+1][lr]=vb.y; Bs[lk+2][lr]=vb.z; Bs[lk+3][lr]=vb.w;
        __syncthreads();
#pragma unroll
        for (int k = 0; k < 8; k++) {
            float a[8], b[8];
#pragma unroll
            for (int i = 0; i < 8; i++) a[i] = As[k][ty*8 + i];
#pragma unroll
            for (int j = 0; j < 8; j++) b[j] = Bs[k][tx*8 + j];
#pragma unroll
            for (int i = 0; i < 8; i++)
#pragma unroll
                for (int j = 0; j < 8; j++) acc[i][j] += a[i] * b[j];
        }
    }
#pragma unroll
    for (int i = 0; i < 8; i++) {
        int gm = m0 + ty*8 + i;
        if (gm >= M) continue;
#pragma unroll
        for (int j = 0; j < 8; j++) {
            int gn = n0 + tx*8 + j;
            if (gn >= N) continue;
            C[(size_t)gm * N + gn] = acc[i][j];
        }
    }
}

// ===================== fused attention (fp32, split-bf16 epilogue) =====================
__global__ void __launch_bounds__(256)
attn_k(const float* __restrict__ qkv, __nv_bfloat16* __restrict__ ctx2) {
    __shared__ float Ks[64*64];
    __shared__ float Vs[64*64];
    __shared__ float Ss[32*64];

    int tid = threadIdx.x;
    int q0 = blockIdx.x * 32;
    int bh = blockIdx.y;
    int b = bh / HEADS_, hh = bh - b*HEADS_;
    const float* base = qkv + (size_t)b * S_ * TRID_ + hh * HD_;

    int q = tid >> 3, lane8 = tid & 7;
    int qg = q0 + q;
    int qsw = (q & 7) << 3;

    ull qp[32];
    if (qg < S_) {
        const float* qrow = base + (size_t)qg * TRID_;
#pragma unroll
        for (int d4 = 0; d4 < 16; d4++) {
            float4 v = *(const float4*)(qrow + d4*4);
            qp[2*d4]   = pack2(v.x * 0.125f, v.y * 0.125f);
            qp[2*d4+1] = pack2(v.z * 0.125f, v.w * 0.125f);
        }
    } else {
#pragma unroll
        for (int d = 0; d < 32; d++) qp[d] = 0ull;
    }

    ull Op[4];
#pragma unroll
    for (int e = 0; e < 4; e++) Op[e] = 0ull;
    float m = -1e30f, l = 0.f;

    for (int kt = 0; kt < 4; kt++) {
        __syncthreads();
#pragma unroll
        for (int j = 0; j < 4; j++) {
            int lin = tid + j*256;
            int kk = lin >> 4, d4 = lin & 15;
            int kg = kt*64 + kk;
            float4 kv = make_float4(0.f,0.f,0.f,0.f);
            float4 vv = make_float4(0.f,0.f,0.f,0.f);
            if (kg < S_) {
                kv = *(const float4*)(base + D_  + (size_t)kg * TRID_ + d4*4);
                vv = *(const float4*)(base + 2*D_ + (size_t)kg * TRID_ + d4*4);
            }
            *(float4*)&Ks[kk*64 + ((d4 + kk) & 15) * 4] = kv;
            *(float4*)&Vs[kk*64 + d4*4] = vv;
        }
        __syncthreads();

        float s[8];
#pragma unroll
        for (int j = 0; j < 8; j++) {
            int kk = lane8 + j*8;
            ull sp = 0ull;
#pragma unroll
            for (int d4 = 0; d4 < 16; d4++) {
                ulonglong2 kv = *(const ulonglong2*)&Ks[kk*64 + ((d4 + kk) & 15) * 4];
                ffma2(sp, qp[2*d4],   kv.x);
                ffma2(sp, qp[2*d4+1], kv.y);
            }
            float lo, hi; unpack2(sp, lo, hi);
            int kg = kt*64 + kk;
            s[j] = (kg < S_) ? (lo + hi) : -1e30f;
        }
        float mt = s[0];
#pragma unroll
        for (int j = 1; j < 8; j++) mt = fmaxf(mt, s[j]);
        mt = fmaxf(mt, __shfl_xor_sync(0xffffffffu, mt, 4, 8));
        mt = fmaxf(mt, __shfl_xor_sync(0xffffffffu, mt, 2, 8));
        mt = fmaxf(mt, __shfl_xor_sync(0xffffffffu, mt, 1, 8));
        float mn = fmaxf(m, mt);
        float r = __expf(m - mn);
        float p[8];
        float ls = 0.f;
#pragma unroll
        for (int j = 0; j < 8; j++) { p[j] = __expf(s[j] - mn); ls += p[j]; }
        ls += __shfl_xor_sync(0xffffffffu, ls, 4, 8);
        ls += __shfl_xor_sync(0xffffffffu, ls, 2, 8);
        ls += __shfl_xor_sync(0xffffffffu, ls, 1, 8);
        l = l * r + ls;
        m = mn;
#pragma unroll
        for (int j = 0; j < 8; j++) {
            int kk = lane8 + j*8;
            Ss[q*64 + (kk ^ qsw)] = p[j];
        }
        __syncwarp();
        ull rd = packdup(r);
#pragma unroll
        for (int e = 0; e < 4; e++) mul2(Op[e], rd);
#pragma unroll
        for (int kk = 0; kk < 64; kk++) {
            ull pv = packdup(Ss[q*64 + (kk ^ qsw)]);
            ulonglong2 v0 = *(const ulonglong2*)&Vs[kk*64 + lane8*8];
            ulonglong2 v1 = *(const ulonglong2*)&Vs[kk*64 + lane8*8 + 4];
            ffma2(Op[0], pv, v0.x);
            ffma2(Op[1], pv, v0.y);
            ffma2(Op[2], pv, v1.x);
            ffma2(Op[3], pv, v1.y);
        }
    }

    if (qg < S_) {
        float inv = 1.f / l;
        float O[8];
#pragma unroll
        for (int e = 0; e < 4; e++) unpack2(Op[e], O[2*e], O[2*e+1]);
        size_t rb = (size_t)(b * S_ + qg) * TRID_ + hh * HD_ + lane8*8;
#pragma unroll
        for (int e2 = 0; e2 < 4; e2++) {
            float x0 = O[2*e2] * inv, x1 = O[2*e2+1] * inv;
            __nv_bfloat16 h0, l0, h1, l1;
            split_bf(x0, h0, l0);
            split_bf(x1, h1, l1);
            __nv_bfloat162 hh2; hh2.x = h0; hh2.y = h1;
            __nv_bfloat162 ll2; ll2.x = l0; ll2.y = l1;
            *(__nv_bfloat162*)(ctx2 + rb + 2*e2)        = hh2;
            *(__nv_bfloat162*)(ctx2 + rb + D_ + 2*e2)   = hh2;
            *(__nv_bfloat162*)(ctx2 + rb + 2*D_ + 2*e2) = ll2;
        }
    }
}

// ===================== launch =====================
extern "C" void kernel_launch(void* const* d_in, const int* in_sizes, int n_in,
                              void* d_out, int out_size) {
    const float* x         = (const float*)d_in[0];
    const float* patch_w   = (const float*)d_in[1];
    const float* patch_b   = (const float*)d_in[2];
    const float* cls_token = (const float*)d_in[3];
    const float* pos_embed = (const float*)d_in[4];
    const float* ln1_g     = (const float*)d_in[5];
    const float* ln1_b     = (const float*)d_in[6];
    const float* qkv_w     = (const float*)d_in[7];
    const float* qkv_b     = (const float*)d_in[8];
    const float* out_w     = (const float*)d_in[9];
    const float* out_b     = (const float*)d_in[10];
    const float* ln2_g     = (const float*)d_in[11];
    const float* ln2_b     = (const float*)d_in[12];
    const float* fc1_w     = (const float*)d_in[13];
    const float* fc1_b     = (const float*)d_in[14];
    const float* fc2_w     = (const float*)d_in[15];
    const float* fc2_b     = (const float*)d_in[16];
    const float* lnf_g     = (const float*)d_in[17];
    const float* lnf_b     = (const float*)d_in[18];
    const float* head_w    = (const float*)d_in[19];
    float* out = (float*)d_out;

    float *h, *tok, *qkv, *cls;
    __nv_bfloat16 *x2, *ctx2, *hid2, *p2, *pw2, *qkvw2, *outw2, *fc1w2, *fc2w2;
    cudaGetSymbolAddress((void**)&h,     g_h);
    cudaGetSymbolAddress((void**)&tok,   g_tok);
    cudaGetSymbolAddress((void**)&qkv,   g_qkv);
    cudaGetSymbolAddress((void**)&cls,   g_cls);
    cudaGetSymbolAddress((void**)&x2,    g_x2);
    cudaGetSymbolAddress((void**)&ctx2,  g_ctx2);
    cudaGetSymbolAddress((void**)&hid2,  g_hid2);
    cudaGetSymbolAddress((void**)&p2,    g_p2);
    cudaGetSymbolAddress((void**)&pw2,   g_pw2);
    cudaGetSymbolAddress((void**)&qkvw2, g_qkvw2);
    cudaGetSymbolAddress((void**)&outw2, g_outw2);
    cudaGetSymbolAddress((void**)&fc1w2, g_fc1w2);
    cudaGetSymbolAddress((void**)&fc2w2, g_fc2w2);

    cudaFuncSetAttribute(gemm_mma<0>, cudaFuncAttributeMaxDynamicSharedMemorySize, GMM_SMEM);
    cudaFuncSetAttribute(gemm_mma<1>, cudaFuncAttributeMaxDynamicSharedMemorySize, GMM_SMEM);
    cudaFuncSetAttribute(gemm_mma<2>, cudaFuncAttributeMaxDynamicSharedMemorySize, GMM_SMEM);

    // ---- weight conversion ----
    {
        auto wlaunch = [](const float* src, __nv_bfloat16* dst, int R, int K) {
            size_t n = (size_t)R * K;
            wsplit_k<<<(unsigned)((n + 255) / 256), 256>>>(src, dst, R, K);
        };
        wlaunch(patch_w, pw2, D_, PD_);
        wlaunch(qkv_w, qkvw2, DEPTH_*TRID_, D_);
        wlaunch(out_w, outw2, DEPTH_*D_, D_);
        wlaunch(fc1_w, fc1w2, DEPTH_*HID_, D_);
        wlaunch(fc2_w, fc2w2, DEPTH_*D_, HID_);
    }

    // ---- patch embed ----
    patchify_k<<<(unsigned)(((size_t)BT_*PD_ + 255) / 256), 256>>>(x, p2);
    gemm_mma<0><<<dim3(D_/128, BT_/128), 128, GMM_SMEM>>>(p2, pw2, patch_b, nullptr,
                                                          tok, BT_, D_, 3*PD_);
    assemble_k<<<(T_*D_ + 255)/256, 256>>>(tok, cls_token, pos_embed, h);

    const int lnBlocks = (T_ + 7) / 8;
    for (int L = 0; L < DEPTH_; L++) {
        ln_k<1><<<lnBlocks, 256>>>(h, nullptr, x2, ln1_g + L*D_, ln1_b + L*D_, T_, D_);
        gemm_mma<0><<<dim3(TRID_/128, T_/128), 128, GMM_SMEM>>>(
            x2, qkvw2 + (size_t)L*TRID_*3*D_, qkv_b + L*TRID_, nullptr,
            qkv, T_, TRID_, 3*D_);
        attn_k<<<dim3(7, B_*HEADS_), 256>>>(qkv, ctx2);
        gemm_mma<1><<<dim3(D_/128, T_/128), 128, GMM_SMEM>>>(
            ctx2, outw2 + (size_t)L*D_*3*D_, out_b + L*D_, h,
            h, T_, D_, 3*D_);
        ln_k<1><<<lnBlocks, 256>>>(h, nullptr, x2, ln2_g + L*D_, ln2_b + L*D_, T_, D_);
        gemm_mma<2><<<dim3(HID_/128, T_/128), 128, GMM_SMEM>>>(
            x2, fc1w2 + (size_t)L*HID_*3*D_, fc1_b + L*HID_, nullptr,
            hid2, T_, HID_, 3*D_);
        gemm_mma<1><<<dim3(D_/128, T_/128), 128, GMM_SMEM>>>(
            hid2, fc2w2 + (size_t)L*D_*3*HID_, fc2_b + L*D_, h,
            h, T_, D_, 3*HID_);
    }

    ln_k<0><<<(B_ + 7)/8, 256>>>(h, cls, nullptr, lnf_g, lnf_b, B_, S_*D_);
    gemm32_k<<<dim3(1, 1), 256>>>(cls, head_w, out, B_, NCLS_, D_);
}

// round 8
// speedup vs baseline: 1.0085x; 1.0085x over previous
#include <cuda_runtime.h>
#include <cuda_bf16.h>
#include <cstdint>
#include <cstddef>

#define B_     128
#define C_     3
#define IMG_   224
#define P_     16
#define HP_    14
#define NP_    196
#define S_     197
#define D_     384
#define HEADS_ 6
#define HD_    64
#define DEPTH_ 12
#define HID_   1536
#define NCLS_  100
#define PD_    768
#define T_     (B_*S_)    // 25216
#define BT_    (B_*NP_)   // 25088
#define TRID_  (3*D_)     // 1152

typedef unsigned long long ull;

// ===================== helpers =====================
__device__ __forceinline__ uint32_t smem_u32(const void* p) {
    uint32_t a;
    asm("{ .reg .u64 t; cvta.to.shared.u64 t, %1; cvt.u32.u64 %0, t; }" : "=r"(a) : "l"(p));
    return a;
}
__device__ __forceinline__ void cp16(uint32_t saddr, const void* g) {
    asm volatile("cp.async.cg.shared.global [%0], [%1], 16;" :: "r"(saddr), "l"(g));
}
#define CP_COMMIT() asm volatile("cp.async.commit_group;" ::: "memory")
#define CP_WAIT(n)  asm volatile("cp.async.wait_group %0;" :: "n"(n) : "memory")

__device__ __forceinline__ void ldsm4(uint32_t& r0, uint32_t& r1, uint32_t& r2, uint32_t& r3,
                                      uint32_t a) {
    asm volatile("ldmatrix.sync.aligned.m8n8.x4.shared.b16 {%0,%1,%2,%3}, [%4];"
                 : "=r"(r0), "=r"(r1), "=r"(r2), "=r"(r3) : "r"(a));
}
__device__ __forceinline__ void mma16816(float* c, uint32_t a0, uint32_t a1, uint32_t a2,
                                         uint32_t a3, uint32_t b0, uint32_t b1) {
    asm volatile("mma.sync.aligned.m16n8k16.row.col.f32.bf16.bf16.f32 "
                 "{%0,%1,%2,%3}, {%4,%5,%6,%7}, {%8,%9}, {%0,%1,%2,%3};"
                 : "+f"(c[0]), "+f"(c[1]), "+f"(c[2]), "+f"(c[3])
                 : "r"(a0), "r"(a1), "r"(a2), "r"(a3), "r"(b0), "r"(b1));
}

// f32x2 helpers for attention
__device__ __forceinline__ void ffma2(ull& acc, ull a, ull b) {
    asm("fma.rn.f32x2 %0, %1, %2, %0;" : "+l"(acc) : "l"(a), "l"(b));
}
__device__ __forceinline__ ull packdup(float a) {
    ull r; asm("mov.b64 %0, {%1, %1};" : "=l"(r) : "f"(a)); return r;
}
__device__ __forceinline__ ull pack2(float lo, float hi) {
    ull r; asm("mov.b64 %0, {%1, %2};" : "=l"(r) : "f"(lo), "f"(hi)); return r;
}
__device__ __forceinline__ void unpack2(ull v, float& lo, float& hi) {
    asm("mov.b64 {%0, %1}, %2;" : "=f"(lo), "=f"(hi) : "l"(v));
}
__device__ __forceinline__ void mul2(ull& v, ull s) {
    asm("mul.rn.f32x2 %0, %1, %2;" : "=l"(v) : "l"(v), "l"(s));
}
__device__ __forceinline__ void split_bf(float x, __nv_bfloat16& hi, __nv_bfloat16& lo) {
    hi = __float2bfloat16(x);
    lo = __float2bfloat16(x - __bfloat162float(hi));
}

// ===================== scratch =====================
__device__ float g_h[(size_t)T_*D_];
__device__ float g_tok[(size_t)BT_*D_];
__device__ float g_qkv[(size_t)T_*TRID_];
__device__ float g_cls[B_*D_];
__device__ __nv_bfloat16 g_x2[(size_t)T_*3*D_];
__device__ __nv_bfloat16 g_ctx2[(size_t)T_*3*D_];
__device__ __nv_bfloat16 g_hid2[(size_t)T_*3*HID_];
__device__ __nv_bfloat16 g_p2[(size_t)BT_*3*PD_];
__device__ __nv_bfloat16 g_pw2[(size_t)D_*3*PD_];
__device__ __nv_bfloat16 g_qkvw2[(size_t)DEPTH_*TRID_*3*D_];
__device__ __nv_bfloat16 g_outw2[(size_t)DEPTH_*D_*3*D_];
__device__ __nv_bfloat16 g_fc1w2[(size_t)DEPTH_*HID_*3*D_];
__device__ __nv_bfloat16 g_fc2w2[(size_t)DEPTH_*D_*3*HID_];

// ===================== weight split =====================
__global__ void wsplit_k(const float* __restrict__ src, __nv_bfloat16* __restrict__ dst,
                         int R, int K) {
    size_t idx = (size_t)blockIdx.x * blockDim.x + threadIdx.x;
    if (idx >= (size_t)R * K) return;
    int r = (int)(idx / K), k = (int)(idx - (size_t)r * K);
    __nv_bfloat16 hi, lo;
    split_bf(src[idx], hi, lo);
    size_t rb = (size_t)r * 3 * K;
    dst[rb + k] = hi;
    dst[rb + K + k] = lo;
    dst[rb + 2*K + k] = hi;
}

// ===================== patchify -> split =====================
__global__ void patchify_k(const float* __restrict__ x, __nv_bfloat16* __restrict__ out) {
    size_t idx = (size_t)blockIdx.x * blockDim.x + threadIdx.x;
    if (idx >= (size_t)BT_*PD_) return;
    int t = (int)(idx / PD_), j = (int)(idx - (size_t)t * PD_);
    int b = t / NP_, p = t - b*NP_;
    int ph = p / HP_, pw = p - ph*HP_;
    int c = j >> 8, r = (j >> 4) & 15, col = j & 15;
    float v = x[(((size_t)b*C_ + c)*IMG_ + ph*P_ + r)*IMG_ + pw*P_ + col];
    __nv_bfloat16 hi, lo;
    split_bf(v, hi, lo);
    size_t rb = (size_t)t * 3 * PD_;
    out[rb + j] = hi;
    out[rb + PD_ + j] = hi;
    out[rb + 2*PD_ + j] = lo;
}

// ===================== assemble =====================
__global__ void assemble_k(const float* __restrict__ tok, const float* __restrict__ cls,
                           const float* __restrict__ pos, float* __restrict__ h) {
    int idx = blockIdx.x * blockDim.x + threadIdx.x;
    if (idx >= T_*D_) return;
    int t = idx / D_, d = idx - t*D_;
    int b = t / S_, s = t - b*S_;
    float v = (s == 0) ? cls[d] : tok[(size_t)(b*NP_ + s - 1)*D_ + d];
    h[idx] = v + pos[s*D_ + d];
}

// ===================== layernorm =====================
template <int SPLIT>
__global__ void ln_k(const float* __restrict__ in, float* __restrict__ outf,
                     __nv_bfloat16* __restrict__ out2,
                     const float* __restrict__ g, const float* __restrict__ bta,
                     int rows, int instride) {
    int warp = (blockIdx.x * blockDim.x + threadIdx.x) >> 5;
    int lane = threadIdx.x & 31;
    if (warp >= rows) return;
    const float* row = in + (size_t)warp * instride;
    float v[12];
    float s = 0.f;
#pragma unroll
    for (int i = 0; i < 12; i++) { v[i] = row[lane + i*32]; s += v[i]; }
#pragma unroll
    for (int o = 16; o > 0; o >>= 1) s += __shfl_xor_sync(0xffffffffu, s, o);
    float mean = s * (1.f/384.f);
    float vs = 0.f;
#pragma unroll
    for (int i = 0; i < 12; i++) { float d = v[i] - mean; vs += d*d; }
#pragma unroll
    for (int o = 16; o > 0; o >>= 1) vs += __shfl_xor_sync(0xffffffffu, vs, o);
    float rstd = rsqrtf(vs * (1.f/384.f) + 1e-5f);
    if (SPLIT) {
        size_t rb = (size_t)warp * (3*D_);
#pragma unroll
        for (int i = 0; i < 12; i++) {
            int c = lane + i*32;
            float y = (v[i] - mean) * rstd * g[c] + bta[c];
            __nv_bfloat16 hi, lo;
            split_bf(y, hi, lo);
            out2[rb + c] = hi;
            out2[rb + D_ + c] = hi;
            out2[rb + 2*D_ + c] = lo;
        }
    } else {
        float* orow = outf + (size_t)warp * D_;
#pragma unroll
        for (int i = 0; i < 12; i++) {
            int c = lane + i*32;
            orow[c] = (v[i] - mean) * rstd * g[c] + bta[c];
        }
    }
}

// ===================== mma.sync bf16 GEMM: 256 thr, 8 warps 2x4, 64x32 tile, 4 stages ==
// C[M,N] = A2[M,K2] @ W2[N,K2]^T (+bias)
// MODE 0: fp32 store. MODE 1: fp32 resid add. MODE 2: gelu -> split bf16 [hi,hi,lo].
// SMEM stage: A 128x32 (8KB) + B 128x32 (8KB) = 16KB; 4 stages = 64KB. 2 CTAs/SM.
#define GMM_SMEM 65536
#define STAGE_BYTES 16384
template <int MODE>
__global__ void __launch_bounds__(256, 2)
gemm_mma(const __nv_bfloat16* __restrict__ A, const __nv_bfloat16* __restrict__ W,
         const float* __restrict__ bias, const float* __restrict__ resid,
         void* __restrict__ Cout, int M, int N, int K2) {
    extern __shared__ char dsm[];
    uint32_t sbase = smem_u32(dsm);

    int tid = threadIdx.x;
    int wid = tid >> 5, lane = tid & 31;
    int wm = wid & 1, wn = wid >> 1;        // 2x4 warp grid, 64x32 tiles
    int m0 = blockIdx.y * 128, n0 = blockIdx.x * 128;

    // loader: 2 tasks/thread for A, 2 for B: task = tid + 256*i, r = task>>2, c = task&3
    uint32_t soA[2], soB[2];
    const __nv_bfloat16 *Ag[2], *Wg[2];
#pragma unroll
    for (int i = 0; i < 2; i++) {
        int task = tid + 256*i;
        int r = task >> 2, c = task & 3;
        uint32_t sw = (uint32_t)(c ^ ((r >> 1) & 3));
        soA[i] = r*64 + (sw << 4);
        soB[i] = 8192 + r*64 + (sw << 4);
        Ag[i] = A + (size_t)(m0 + r)*K2 + c*8;
        Wg[i] = W + (size_t)(n0 + r)*K2 + c*8;
    }

    float acc[4][4][4];
#pragma unroll
    for (int f = 0; f < 4; f++)
#pragma unroll
        for (int g = 0; g < 4; g++)
#pragma unroll
            for (int e = 0; e < 4; e++) acc[f][g][e] = 0.f;

    int nc = K2 >> 5;   // chunks of 32

    // prologue: stages 0..2
#pragma unroll
    for (int s = 0; s < 3; s++) {
        if (s < nc) {
            uint32_t st = sbase + (uint32_t)s * STAGE_BYTES;
#pragma unroll
            for (int i = 0; i < 2; i++) {
                cp16(st + soA[i], Ag[i] + (size_t)s*32);
                cp16(st + soB[i], Wg[i] + (size_t)s*32);
            }
        }
        CP_COMMIT();
    }

    for (int ch = 0; ch < nc; ch++) {
        CP_WAIT(2);
        __syncthreads();
        {
            int nst = ch + 3;
            if (nst < nc) {
                uint32_t st = sbase + (uint32_t)(nst & 3) * STAGE_BYTES;
#pragma unroll
                for (int i = 0; i < 2; i++) {
                    cp16(st + soA[i], Ag[i] + (size_t)nst*32);
                    cp16(st + soB[i], Wg[i] + (size_t)nst*32);
                }
            }
            CP_COMMIT();
        }
        uint32_t st = sbase + (uint32_t)(ch & 3) * STAGE_BYTES;
#pragma unroll
        for (int ks = 0; ks < 2; ks++) {
            uint32_t a[4][4];
#pragma unroll
            for (int f = 0; f < 4; f++) {
                int r = wm*64 + f*16 + (lane & 15);
                int kc = ks*2 + (lane >> 4);
                uint32_t addr = st + r*64 + (((uint32_t)(kc ^ ((r >> 1) & 3))) << 4);
                ldsm4(a[f][0], a[f][1], a[f][2], a[f][3], addr);
            }
            uint32_t b[2][4];
#pragma unroll
            for (int g2 = 0; g2 < 2; g2++) {
                int nr = wn*32 + g2*16 + ((lane >> 4) << 3) + (lane & 7);
                int kc = ks*2 + ((lane >> 3) & 1);
                uint32_t addr = st + 8192 + nr*64 + (((uint32_t)(kc ^ ((nr >> 1) & 3))) << 4);
                ldsm4(b[g2][0], b[g2][1], b[g2][2], b[g2][3], addr);
            }
#pragma unroll
            for (int f = 0; f < 4; f++)
#pragma unroll
                for (int g = 0; g < 4; g++)
                    mma16816(acc[f][g], a[f][0], a[f][1], a[f][2], a[f][3],
                             b[g >> 1][(g & 1)*2], b[g >> 1][(g & 1)*2 + 1]);
        }
    }

    // epilogue
#pragma unroll
    for (int f = 0; f < 4; f++) {
        int m = m0 + wm*64 + f*16 + (lane >> 2);
#pragma unroll
        for (int g = 0; g < 4; g++) {
            int n = n0 + wn*32 + g*8 + (lane & 3)*2;
            float bn0 = bias[n], bn1 = bias[n + 1];
            float v00 = acc[f][g][0] + bn0, v01 = acc[f][g][1] + bn1;
            float v10 = acc[f][g][2] + bn0, v11 = acc[f][g][3] + bn1;
            if (MODE == 1) {
                const float* r0p = resid + (size_t)m*N + n;
                const float* r1p = resid + (size_t)(m + 8)*N + n;
                v00 += r0p[0]; v01 += r0p[1];
                v10 += r1p[0]; v11 += r1p[1];
            }
            if (MODE == 2) {
                v00 = 0.5f * v00 * (1.f + erff(v00 * 0.70710678118654752f));
                v01 = 0.5f * v01 * (1.f + erff(v01 * 0.70710678118654752f));
                v10 = 0.5f * v10 * (1.f + erff(v10 * 0.70710678118654752f));
                v11 = 0.5f * v11 * (1.f + erff(v11 * 0.70710678118654752f));
                __nv_bfloat16* H = (__nv_bfloat16*)Cout;
                size_t rb0 = (size_t)m * (3*N), rb1 = (size_t)(m + 8) * (3*N);
                __nv_bfloat16 h0, l0, h1, l1;
                split_bf(v00, h0, l0); split_bf(v01, h1, l1);
                __nv_bfloat162 hh, llv;
                hh.x = h0; hh.y = h1; llv.x = l0; llv.y = l1;
                *(__nv_bfloat162*)(H + rb0 + n)       = hh;
                *(__nv_bfloat162*)(H + rb0 + N + n)   = hh;
                *(__nv_bfloat162*)(H + rb0 + 2*N + n) = llv;
                split_bf(v10, h0, l0); split_bf(v11, h1, l1);
                hh.x = h0; hh.y = h1; llv.x = l0; llv.y = l1;
                *(__nv_bfloat162*)(H + rb1 + n)       = hh;
                *(__nv_bfloat162*)(H + rb1 + N + n)   = hh;
                *(__nv_bfloat162*)(H + rb1 + 2*N + n) = llv;
            } else {
                float* Cf = (float*)Cout;
                *(float2*)(Cf + (size_t)m*N + n)       = make_float2(v00, v01);
                *(float2*)(Cf + (size_t)(m + 8)*N + n) = make_float2(v10, v11);
            }
        }
    }
}

// ===================== fp32 GEMM for head only =====================
__global__ void __launch_bounds__(256)
gemm32_k(const float* __restrict__ A, const float* __restrict__ W,
         float* __restrict__ C, int M, int N, int K) {
    __shared__ float As[8][132];
    __shared__ float Bs[8][132];
    int tid = threadIdx.x;
    int m0 = blockIdx.y * 128, n0 = blockIdx.x * 128;
    int ty = tid >> 4, tx = tid & 15;
    int lr = tid >> 1;
    int lk = (tid & 1) * 4;
    float acc[8][8];
#pragma unroll
    for (int i = 0; i < 8; i++)
#pragma unroll
        for (int j = 0; j < 8; j++) acc[i][j] = 0.f;
    bool av = (m0 + lr) < M;
    bool wv = (n0 + lr) < N;
    const float* Aptr = A + (size_t)(m0 + lr) * K + lk;
    const float* Wptr = W + (size_t)(n0 + lr) * K + lk;
    for (int k0 = 0; k0 < K; k0 += 8) {
        float4 va = av ? *(const float4*)(Aptr + k0) : make_float4(0.f,0.f,0.f,0.f);
        float4 vb = wv ? *(const float4*)(Wptr + k0) : make_float4(0.f,0.f,0.f,0.f);
        __syncthreads();
        As[lk+0][lr]=va.x; As[lk+1][lr]=va.y; As[lk+2][lr]=va.z; As[lk+3][lr]=va.w;
        Bs[lk+0][lr]=vb.x; Bs[lk+1][lr]=vb.y; Bs[lk+2][lr]=vb.z; Bs[lk+3][lr]=vb.w;
        __syncthreads();
#pragma unroll
        for (int k = 0; k < 8; k++) {
            float a[8], b[8];
#pragma unroll
            for (int i = 0; i < 8; i++) a[i] = As[k][ty*8 + i];
#pragma unroll
            for (int j = 0; j < 8; j++) b[j] = Bs[k][tx*8 + j];
#pragma unroll
            for (int i = 0; i < 8; i++)
#pragma unroll
                for (int j = 0; j < 8; j++) acc[i][j] += a[i] * b[j];
        }
    }
#pragma unroll
    for (int i = 0; i < 8; i++) {
        int gm = m0 + ty*8 + i;
        if (gm >= M) continue;
#pragma unroll
        for (int j = 0; j < 8; j++) {
            int gn = n0 + tx*8 + j;
            if (gn >= N) continue;
            C[(size_t)gm * N + gn] = acc[i][j];
        }
    }
}

// ===================== fused attention (fp32, split-bf16 epilogue) =====================
__global__ void __launch_bounds__(256)
attn_k(const float* __restrict__ qkv, __nv_bfloat16* __restrict__ ctx2) {
    __shared__ float Ks[64*64];
    __shared__ float Vs[64*64];
    __shared__ float Ss[32*64];

    int tid = threadIdx.x;
    int q0 = blockIdx.x * 32;
    int bh = blockIdx.y;
    int b = bh / HEADS_, hh = bh - b*HEADS_;
    const float* base = qkv + (size_t)b * S_ * TRID_ + hh * HD_;

    int q = tid >> 3, lane8 = tid & 7;
    int qg = q0 + q;
    int qsw = (q & 7) << 3;

    ull qp[32];
    if (qg < S_) {
        const float* qrow = base + (size_t)qg * TRID_;
#pragma unroll
        for (int d4 = 0; d4 < 16; d4++) {
            float4 v = *(const float4*)(qrow + d4*4);
            qp[2*d4]   = pack2(v.x * 0.125f, v.y * 0.125f);
            qp[2*d4+1] = pack2(v.z * 0.125f, v.w * 0.125f);
        }
    } else {
#pragma unroll
        for (int d = 0; d < 32; d++) qp[d] = 0ull;
    }

    ull Op[4];
#pragma unroll
    for (int e = 0; e < 4; e++) Op[e] = 0ull;
    float m = -1e30f, l = 0.f;

    for (int kt = 0; kt < 4; kt++) {
        __syncthreads();
#pragma unroll
        for (int j = 0; j < 4; j++) {
            int lin = tid + j*256;
            int kk = lin >> 4, d4 = lin & 15;
            int kg = kt*64 + kk;
            float4 kv = make_float4(0.f,0.f,0.f,0.f);
            float4 vv = make_float4(0.f,0.f,0.f,0.f);
            if (kg < S_) {
                kv = *(const float4*)(base + D_  + (size_t)kg * TRID_ + d4*4);
                vv = *(const float4*)(base + 2*D_ + (size_t)kg * TRID_ + d4*4);
            }
            *(float4*)&Ks[kk*64 + ((d4 + kk) & 15) * 4] = kv;
            *(float4*)&Vs[kk*64 + d4*4] = vv;
        }
        __syncthreads();

        float s[8];
#pragma unroll
        for (int j = 0; j < 8; j++) {
            int kk = lane8 + j*8;
            ull sp = 0ull;
#pragma unroll
            for (int d4 = 0; d4 < 16; d4++) {
                ulonglong2 kv = *(const ulonglong2*)&Ks[kk*64 + ((d4 + kk) & 15) * 4];
                ffma2(sp, qp[2*d4],   kv.x);
                ffma2(sp, qp[2*d4+1], kv.y);
            }
            float lo, hi; unpack2(sp, lo, hi);
            int kg = kt*64 + kk;
            s[j] = (kg < S_) ? (lo + hi) : -1e30f;
        }
        float mt = s[0];
#pragma unroll
        for (int j = 1; j < 8; j++) mt = fmaxf(mt, s[j]);
        mt = fmaxf(mt, __shfl_xor_sync(0xffffffffu, mt, 4, 8));
        mt = fmaxf(mt, __shfl_xor_sync(0xffffffffu, mt, 2, 8));
        mt = fmaxf(mt, __shfl_xor_sync(0xffffffffu, mt, 1, 8));
        float mn = fmaxf(m, mt);
        float r = __expf(m - mn);
        float p[8];
        float ls = 0.f;
#pragma unroll
        for (int j = 0; j < 8; j++) { p[j] = __expf(s[j] - mn); ls += p[j]; }
        ls += __shfl_xor_sync(0xffffffffu, ls, 4, 8);
        ls += __shfl_xor_sync(0xffffffffu, ls, 2, 8);
        ls += __shfl_xor_sync(0xffffffffu, ls, 1, 8);
        l = l * r + ls;
        m = mn;
#pragma unroll
        for (int j = 0; j < 8; j++) {
            int kk = lane8 + j*8;
            Ss[q*64 + (kk ^ qsw)] = p[j];
        }
        __syncwarp();
        ull rd = packdup(r);
#pragma unroll
        for (int e = 0; e < 4; e++) mul2(Op[e], rd);
#pragma unroll
        for (int kk = 0; kk < 64; kk++) {
            ull pv = packdup(Ss[q*64 + (kk ^ qsw)]);
            ulonglong2 v0 = *(const ulonglong2*)&Vs[kk*64 + lane8*8];
            ulonglong2 v1 = *(const ulonglong2*)&Vs[kk*64 + lane8*8 + 4];
            ffma2(Op[0], pv, v0.x);
            ffma2(Op[1], pv, v0.y);
            ffma2(Op[2], pv, v1.x);
            ffma2(Op[3], pv, v1.y);
        }
    }

    if (qg < S_) {
        float inv = 1.f / l;
        float O[8];
#pragma unroll
        for (int e = 0; e < 4; e++) unpack2(Op[e], O[2*e], O[2*e+1]);
        size_t rb = (size_t)(b * S_ + qg) * TRID_ + hh * HD_ + lane8*8;
#pragma unroll
        for (int e2 = 0; e2 < 4; e2++) {
            float x0 = O[2*e2] * inv, x1 = O[2*e2+1] * inv;
            __nv_bfloat16 h0, l0, h1, l1;
            split_bf(x0, h0, l0);
            split_bf(x1, h1, l1);
            __nv_bfloat162 hh2; hh2.x = h0; hh2.y = h1;
            __nv_bfloat162 ll2; ll2.x = l0; ll2.y = l1;
            *(__nv_bfloat162*)(ctx2 + rb + 2*e2)        = hh2;
            *(__nv_bfloat162*)(ctx2 + rb + D_ + 2*e2)   = hh2;
            *(__nv_bfloat162*)(ctx2 + rb + 2*D_ + 2*e2) = ll2;
        }
    }
}

// ===================== launch =====================
extern "C" void kernel_launch(void* const* d_in, const int* in_sizes, int n_in,
                              void* d_out, int out_size) {
    const float* x         = (const float*)d_in[0];
    const float* patch_w   = (const float*)d_in[1];
    const float* patch_b   = (const float*)d_in[2];
    const float* cls_token = (const float*)d_in[3];
    const float* pos_embed = (const float*)d_in[4];
    const float* ln1_g     = (const float*)d_in[5];
    const float* ln1_b     = (const float*)d_in[6];
    const float* qkv_w     = (const float*)d_in[7];
    const float* qkv_b     = (const float*)d_in[8];
    const float* out_w     = (const float*)d_in[9];
    const float* out_b     = (const float*)d_in[10];
    const float* ln2_g     = (const float*)d_in[11];
    const float* ln2_b     = (const float*)d_in[12];
    const float* fc1_w     = (const float*)d_in[13];
    const float* fc1_b     = (const float*)d_in[14];
    const float* fc2_w     = (const float*)d_in[15];
    const float* fc2_b     = (const float*)d_in[16];
    const float* lnf_g     = (const float*)d_in[17];
    const float* lnf_b     = (const float*)d_in[18];
    const float* head_w    = (const float*)d_in[19];
    float* out = (float*)d_out;

    float *h, *tok, *qkv, *cls;
    __nv_bfloat16 *x2, *ctx2, *hid2, *p2, *pw2, *qkvw2, *outw2, *fc1w2, *fc2w2;
    cudaGetSymbolAddress((void**)&h,     g_h);
    cudaGetSymbolAddress((void**)&tok,   g_tok);
    cudaGetSymbolAddress((void**)&qkv,   g_qkv);
    cudaGetSymbolAddress((void**)&cls,   g_cls);
    cudaGetSymbolAddress((void**)&x2,    g_x2);
    cudaGetSymbolAddress((void**)&ctx2,  g_ctx2);
    cudaGetSymbolAddress((void**)&hid2,  g_hid2);
    cudaGetSymbolAddress((void**)&p2,    g_p2);
    cudaGetSymbolAddress((void**)&pw2,   g_pw2);
    cudaGetSymbolAddress((void**)&qkvw2, g_qkvw2);
    cudaGetSymbolAddress((void**)&outw2, g_outw2);
    cudaGetSymbolAddress((void**)&fc1w2, g_fc1w2);
    cudaGetSymbolAddress((void**)&fc2w2, g_fc2w2);

    cudaFuncSetAttribute(gemm_mma<0>, cudaFuncAttributeMaxDynamicSharedMemorySize, GMM_SMEM);
    cudaFuncSetAttribute(gemm_mma<1>, cudaFuncAttributeMaxDynamicSharedMemorySize, GMM_SMEM);
    cudaFuncSetAttribute(gemm_mma<2>, cudaFuncAttributeMaxDynamicSharedMemorySize, GMM_SMEM);

    auto wlaunch = [](const float* src, __nv_bfloat16* dst, int R, int K) {
        size_t n = (size_t)R * K;
        wsplit_k<<<(unsigned)((n + 255) / 256), 256>>>(src, dst, R, K);
    };

    // Launch order chosen so USER LAUNCH #4 is a gemm_mma (ncu -s 5 captures it):
    wlaunch(patch_w, pw2, D_, PD_);                                      // 1
    patchify_k<<<(unsigned)(((size_t)BT_*PD_ + 255) / 256), 256>>>(x, p2); // 2
    wlaunch(qkv_w, qkvw2, DEPTH_*TRID_, D_);                             // 3
    gemm_mma<0><<<dim3(D_/128, BT_/128), 256, GMM_SMEM>>>(p2, pw2, patch_b, nullptr,
                                                          tok, BT_, D_, 3*PD_); // 4 <- profiled
    wlaunch(out_w, outw2, DEPTH_*D_, D_);
    wlaunch(fc1_w, fc1w2, DEPTH_*HID_, D_);
    wlaunch(fc2_w, fc2w2, DEPTH_*D_, HID_);
    assemble_k<<<(T_*D_ + 255)/256, 256>>>(tok, cls_token, pos_embed, h);

    const int lnBlocks = (T_ + 7) / 8;
    for (int L = 0; L < DEPTH_; L++) {
        ln_k<1><<<lnBlocks, 256>>>(h, nullptr, x2, ln1_g + L*D_, ln1_b + L*D_, T_, D_);
        gemm_mma<0><<<dim3(TRID_/128, T_/128), 256, GMM_SMEM>>>(
            x2, qkvw2 + (size_t)L*TRID_*3*D_, qkv_b + L*TRID_, nullptr,
            qkv, T_, TRID_, 3*D_);
        attn_k<<<dim3(7, B_*HEADS_), 256>>>(qkv, ctx2);
        gemm_mma<1><<<dim3(D_/128, T_/128), 256, GMM_SMEM>>>(
            ctx2, outw2 + (size_t)L*D_*3*D_, out_b + L*D_, h,
            h, T_, D_, 3*D_);
        ln_k<1><<<lnBlocks, 256>>>(h, nullptr, x2, ln2_g + L*D_, ln2_b + L*D_, T_, D_);
        gemm_mma<2><<<dim3(HID_/128, T_/128), 256, GMM_SMEM>>>(
            x2, fc1w2 + (size_t)L*HID_*3*D_, fc1_b + L*HID_, nullptr,
            hid2, T_, HID_, 3*D_);
        gemm_mma<1><<<dim3(D_/128, T_/128), 256, GMM_SMEM>>>(
            hid2, fc2w2 + (size_t)L*D_*3*HID_, fc2_b + L*D_, h,
            h, T_, D_, 3*HID_);
    }

    ln_k<0><<<(B_ + 7)/8, 256>>>(h, cls, nullptr, lnf_g, lnf_b, B_, S_*D_);
    gemm32_k<<<dim3(1, 1), 256>>>(cls, head_w, out, B_, NCLS_, D_);
}

// round 9
// speedup vs baseline: 1.9379x; 1.9216x over previous
#include <cuda_runtime.h>
#include <cuda_bf16.h>
#include <cstdint>
#include <cstddef>

#define B_     128
#define C_     3
#define IMG_   224
#define P_     16
#define HP_    14
#define NP_    196
#define S_     197
#define D_     384
#define HEADS_ 6
#define HD_    64
#define DEPTH_ 12
#define HID_   1536
#define NCLS_  100
#define PD_    768
#define T_     (B_*S_)    // 25216
#define BT_    (B_*NP_)   // 25088
#define TRID_  (3*D_)     // 1152

typedef unsigned long long ull;

// ===================== helpers =====================
__device__ __forceinline__ uint32_t smem_u32(const void* p) {
    uint32_t a;
    asm("{ .reg .u64 t; cvta.to.shared.u64 t, %1; cvt.u32.u64 %0, t; }" : "=r"(a) : "l"(p));
    return a;
}
__device__ __forceinline__ void cp16(uint32_t saddr, const void* g) {
    asm volatile("cp.async.cg.shared.global [%0], [%1], 16;" :: "r"(saddr), "l"(g));
}
#define CP_COMMIT() asm volatile("cp.async.commit_group;" ::: "memory")
#define CP_WAIT(n)  asm volatile("cp.async.wait_group %0;" :: "n"(n) : "memory")

__device__ __forceinline__ void ldsm4(uint32_t& r0, uint32_t& r1, uint32_t& r2, uint32_t& r3,
                                      uint32_t a) {
    asm volatile("ldmatrix.sync.aligned.m8n8.x4.shared.b16 {%0,%1,%2,%3}, [%4];"
                 : "=r"(r0), "=r"(r1), "=r"(r2), "=r"(r3) : "r"(a));
}
__device__ __forceinline__ void ldsm4t(uint32_t& r0, uint32_t& r1, uint32_t& r2, uint32_t& r3,
                                       uint32_t a) {
    asm volatile("ldmatrix.sync.aligned.m8n8.x4.trans.shared.b16 {%0,%1,%2,%3}, [%4];"
                 : "=r"(r0), "=r"(r1), "=r"(r2), "=r"(r3) : "r"(a));
}
__device__ __forceinline__ void mma16816(float* c, uint32_t a0, uint32_t a1, uint32_t a2,
                                         uint32_t a3, uint32_t b0, uint32_t b1) {
    asm volatile("mma.sync.aligned.m16n8k16.row.col.f32.bf16.bf16.f32 "
                 "{%0,%1,%2,%3}, {%4,%5,%6,%7}, {%8,%9}, {%0,%1,%2,%3};"
                 : "+f"(c[0]), "+f"(c[1]), "+f"(c[2]), "+f"(c[3])
                 : "r"(a0), "r"(a1), "r"(a2), "r"(a3), "r"(b0), "r"(b1));
}
__device__ __forceinline__ void split_bf(float x, __nv_bfloat16& hi, __nv_bfloat16& lo) {
    hi = __float2bfloat16(x);
    lo = __float2bfloat16(x - __bfloat162float(hi));
}
__device__ __forceinline__ uint32_t pk2(__nv_bfloat16 a, __nv_bfloat16 b) {
    __nv_bfloat162 t; t.x = a; t.y = b;
    return *reinterpret_cast<uint32_t*>(&t);
}

// ===================== scratch =====================
__device__ float g_h[(size_t)T_*D_];
__device__ float g_tok[(size_t)BT_*D_];
__device__ float g_qkv[(size_t)T_*TRID_];
__device__ float g_cls[B_*D_];
__device__ __nv_bfloat16 g_x2[(size_t)T_*3*D_];
__device__ __nv_bfloat16 g_ctx2[(size_t)T_*3*D_];
__device__ __nv_bfloat16 g_hid2[(size_t)T_*3*HID_];
__device__ __nv_bfloat16 g_p2[(size_t)BT_*3*PD_];
__device__ __nv_bfloat16 g_pw2[(size_t)D_*3*PD_];
__device__ __nv_bfloat16 g_qkvw2[(size_t)DEPTH_*TRID_*3*D_];
__device__ __nv_bfloat16 g_outw2[(size_t)DEPTH_*D_*3*D_];
__device__ __nv_bfloat16 g_fc1w2[(size_t)DEPTH_*HID_*3*D_];
__device__ __nv_bfloat16 g_fc2w2[(size_t)DEPTH_*D_*3*HID_];

// ===================== weight split =====================
__global__ void wsplit_k(const float* __restrict__ src, __nv_bfloat16* __restrict__ dst,
                         int R, int K) {
    size_t idx = (size_t)blockIdx.x * blockDim.x + threadIdx.x;
    if (idx >= (size_t)R * K) return;
    int r = (int)(idx / K), k = (int)(idx - (size_t)r * K);
    __nv_bfloat16 hi, lo;
    split_bf(src[idx], hi, lo);
    size_t rb = (size_t)r * 3 * K;
    dst[rb + k] = hi;
    dst[rb + K + k] = lo;
    dst[rb + 2*K + k] = hi;
}

// ===================== patchify -> split =====================
__global__ void patchify_k(const float* __restrict__ x, __nv_bfloat16* __restrict__ out) {
    size_t idx = (size_t)blockIdx.x * blockDim.x + threadIdx.x;
    if (idx >= (size_t)BT_*PD_) return;
    int t = (int)(idx / PD_), j = (int)(idx - (size_t)t * PD_);
    int b = t / NP_, p = t - b*NP_;
    int ph = p / HP_, pw = p - ph*HP_;
    int c = j >> 8, r = (j >> 4) & 15, col = j & 15;
    float v = x[(((size_t)b*C_ + c)*IMG_ + ph*P_ + r)*IMG_ + pw*P_ + col];
    __nv_bfloat16 hi, lo;
    split_bf(v, hi, lo);
    size_t rb = (size_t)t * 3 * PD_;
    out[rb + j] = hi;
    out[rb + PD_ + j] = hi;
    out[rb + 2*PD_ + j] = lo;
}

// ===================== assemble =====================
__global__ void assemble_k(const float* __restrict__ tok, const float* __restrict__ cls,
                           const float* __restrict__ pos, float* __restrict__ h) {
    int idx = blockIdx.x * blockDim.x + threadIdx.x;
    if (idx >= T_*D_) return;
    int t = idx / D_, d = idx - t*D_;
    int b = t / S_, s = t - b*S_;
    float v = (s == 0) ? cls[d] : tok[(size_t)(b*NP_ + s - 1)*D_ + d];
    h[idx] = v + pos[s*D_ + d];
}

// ===================== layernorm =====================
template <int SPLIT>
__global__ void ln_k(const float* __restrict__ in, float* __restrict__ outf,
                     __nv_bfloat16* __restrict__ out2,
                     const float* __restrict__ g, const float* __restrict__ bta,
                     int rows, int instride) {
    int warp = (blockIdx.x * blockDim.x + threadIdx.x) >> 5;
    int lane = threadIdx.x & 31;
    if (warp >= rows) return;
    const float* row = in + (size_t)warp * instride;
    float v[12];
    float s = 0.f;
#pragma unroll
    for (int i = 0; i < 12; i++) { v[i] = row[lane + i*32]; s += v[i]; }
#pragma unroll
    for (int o = 16; o > 0; o >>= 1) s += __shfl_xor_sync(0xffffffffu, s, o);
    float mean = s * (1.f/384.f);
    float vs = 0.f;
#pragma unroll
    for (int i = 0; i < 12; i++) { float d = v[i] - mean; vs += d*d; }
#pragma unroll
    for (int o = 16; o > 0; o >>= 1) vs += __shfl_xor_sync(0xffffffffu, vs, o);
    float rstd = rsqrtf(vs * (1.f/384.f) + 1e-5f);
    if (SPLIT) {
        size_t rb = (size_t)warp * (3*D_);
#pragma unroll
        for (int i = 0; i < 12; i++) {
            int c = lane + i*32;
            float y = (v[i] - mean) * rstd * g[c] + bta[c];
            __nv_bfloat16 hi, lo;
            split_bf(y, hi, lo);
            out2[rb + c] = hi;
            out2[rb + D_ + c] = hi;
            out2[rb + 2*D_ + c] = lo;
        }
    } else {
        float* orow = outf + (size_t)warp * D_;
#pragma unroll
        for (int i = 0; i < 12; i++) {
            int c = lane + i*32;
            orow[c] = (v[i] - mean) * rstd * g[c] + bta[c];
        }
    }
}

// ===================== mma.sync bf16 GEMM (unchanged from R8) =====================
#define GMM_SMEM 65536
#define STAGE_BYTES 16384
template <int MODE>
__global__ void __launch_bounds__(256, 2)
gemm_mma(const __nv_bfloat16* __restrict__ A, const __nv_bfloat16* __restrict__ W,
         const float* __restrict__ bias, const float* __restrict__ resid,
         void* __restrict__ Cout, int M, int N, int K2) {
    extern __shared__ char dsm[];
    uint32_t sbase = smem_u32(dsm);

    int tid = threadIdx.x;
    int wid = tid >> 5, lane = tid & 31;
    int wm = wid & 1, wn = wid >> 1;
    int m0 = blockIdx.y * 128, n0 = blockIdx.x * 128;

    uint32_t soA[2], soB[2];
    const __nv_bfloat16 *Ag[2], *Wg[2];
#pragma unroll
    for (int i = 0; i < 2; i++) {
        int task = tid + 256*i;
        int r = task >> 2, c = task & 3;
        uint32_t sw = (uint32_t)(c ^ ((r >> 1) & 3));
        soA[i] = r*64 + (sw << 4);
        soB[i] = 8192 + r*64 + (sw << 4);
        Ag[i] = A + (size_t)(m0 + r)*K2 + c*8;
        Wg[i] = W + (size_t)(n0 + r)*K2 + c*8;
    }

    float acc[4][4][4];
#pragma unroll
    for (int f = 0; f < 4; f++)
#pragma unroll
        for (int g = 0; g < 4; g++)
#pragma unroll
            for (int e = 0; e < 4; e++) acc[f][g][e] = 0.f;

    int nc = K2 >> 5;

#pragma unroll
    for (int s = 0; s < 3; s++) {
        if (s < nc) {
            uint32_t st = sbase + (uint32_t)s * STAGE_BYTES;
#pragma unroll
            for (int i = 0; i < 2; i++) {
                cp16(st + soA[i], Ag[i] + (size_t)s*32);
                cp16(st + soB[i], Wg[i] + (size_t)s*32);
            }
        }
        CP_COMMIT();
    }

    for (int ch = 0; ch < nc; ch++) {
        CP_WAIT(2);
        __syncthreads();
        {
            int nst = ch + 3;
            if (nst < nc) {
                uint32_t st = sbase + (uint32_t)(nst & 3) * STAGE_BYTES;
#pragma unroll
                for (int i = 0; i < 2; i++) {
                    cp16(st + soA[i], Ag[i] + (size_t)nst*32);
                    cp16(st + soB[i], Wg[i] + (size_t)nst*32);
                }
            }
            CP_COMMIT();
        }
        uint32_t st = sbase + (uint32_t)(ch & 3) * STAGE_BYTES;
#pragma unroll
        for (int ks = 0; ks < 2; ks++) {
            uint32_t a[4][4];
#pragma unroll
            for (int f = 0; f < 4; f++) {
                int r = wm*64 + f*16 + (lane & 15);
                int kc = ks*2 + (lane >> 4);
                uint32_t addr = st + r*64 + (((uint32_t)(kc ^ ((r >> 1) & 3))) << 4);
                ldsm4(a[f][0], a[f][1], a[f][2], a[f][3], addr);
            }
            uint32_t b[2][4];
#pragma unroll
            for (int g2 = 0; g2 < 2; g2++) {
                int nr = wn*32 + g2*16 + ((lane >> 4) << 3) + (lane & 7);
                int kc = ks*2 + ((lane >> 3) & 1);
                uint32_t addr = st + 8192 + nr*64 + (((uint32_t)(kc ^ ((nr >> 1) & 3))) << 4);
                ldsm4(b[g2][0], b[g2][1], b[g2][2], b[g2][3], addr);
            }
#pragma unroll
            for (int f = 0; f < 4; f++)
#pragma unroll
                for (int g = 0; g < 4; g++)
                    mma16816(acc[f][g], a[f][0], a[f][1], a[f][2], a[f][3],
                             b[g >> 1][(g & 1)*2], b[g >> 1][(g & 1)*2 + 1]);
        }
    }

#pragma unroll
    for (int f = 0; f < 4; f++) {
        int m = m0 + wm*64 + f*16 + (lane >> 2);
#pragma unroll
        for (int g = 0; g < 4; g++) {
            int n = n0 + wn*32 + g*8 + (lane & 3)*2;
            float bn0 = bias[n], bn1 = bias[n + 1];
            float v00 = acc[f][g][0] + bn0, v01 = acc[f][g][1] + bn1;
            float v10 = acc[f][g][2] + bn0, v11 = acc[f][g][3] + bn1;
            if (MODE == 1) {
                const float* r0p = resid + (size_t)m*N + n;
                const float* r1p = resid + (size_t)(m + 8)*N + n;
                v00 += r0p[0]; v01 += r0p[1];
                v10 += r1p[0]; v11 += r1p[1];
            }
            if (MODE == 2) {
                v00 = 0.5f * v00 * (1.f + erff(v00 * 0.70710678118654752f));
                v01 = 0.5f * v01 * (1.f + erff(v01 * 0.70710678118654752f));
                v10 = 0.5f * v10 * (1.f + erff(v10 * 0.70710678118654752f));
                v11 = 0.5f * v11 * (1.f + erff(v11 * 0.70710678118654752f));
                __nv_bfloat16* H = (__nv_bfloat16*)Cout;
                size_t rb0 = (size_t)m * (3*N), rb1 = (size_t)(m + 8) * (3*N);
                __nv_bfloat16 h0, l0, h1, l1;
                split_bf(v00, h0, l0); split_bf(v01, h1, l1);
                uint32_t hh = pk2(h0, h1), llv = pk2(l0, l1);
                *(uint32_t*)((__nv_bfloat16*)H + rb0 + n)       = hh;
                *(uint32_t*)((__nv_bfloat16*)H + rb0 + N + n)   = hh;
                *(uint32_t*)((__nv_bfloat16*)H + rb0 + 2*N + n) = llv;
                split_bf(v10, h0, l0); split_bf(v11, h1, l1);
                hh = pk2(h0, h1); llv = pk2(l0, l1);
                *(uint32_t*)((__nv_bfloat16*)H + rb1 + n)       = hh;
                *(uint32_t*)((__nv_bfloat16*)H + rb1 + N + n)   = hh;
                *(uint32_t*)((__nv_bfloat16*)H + rb1 + 2*N + n) = llv;
            } else {
                float* Cf = (float*)Cout;
                *(float2*)(Cf + (size_t)m*N + n)       = make_float2(v00, v01);
                *(float2*)(Cf + (size_t)(m + 8)*N + n) = make_float2(v10, v11);
            }
        }
    }
}

// ===================== fp32 GEMM for head only =====================
__global__ void __launch_bounds__(256)
gemm32_k(const float* __restrict__ A, const float* __restrict__ W,
         float* __restrict__ C, int M, int N, int K) {
    __shared__ float As[8][132];
    __shared__ float Bs[8][132];
    int tid = threadIdx.x;
    int m0 = blockIdx.y * 128, n0 = blockIdx.x * 128;
    int ty = tid >> 4, tx = tid & 15;
    int lr = tid >> 1;
    int lk = (tid & 1) * 4;
    float acc[8][8];
#pragma unroll
    for (int i = 0; i < 8; i++)
#pragma unroll
        for (int j = 0; j < 8; j++) acc[i][j] = 0.f;
    bool av = (m0 + lr) < M;
    bool wv = (n0 + lr) < N;
    const float* Aptr = A + (size_t)(m0 + lr) * K + lk;
    const float* Wptr = W + (size_t)(n0 + lr) * K + lk;
    for (int k0 = 0; k0 < K; k0 += 8) {
        float4 va = av ? *(const float4*)(Aptr + k0) : make_float4(0.f,0.f,0.f,0.f);
        float4 vb = wv ? *(const float4*)(Wptr + k0) : make_float4(0.f,0.f,0.f,0.f);
        __syncthreads();
        As[lk+0][lr]=va.x; As[lk+1][lr]=va.y; As[lk+2][lr]=va.z; As[lk+3][lr]=va.w;
        Bs[lk+0][lr]=vb.x; Bs[lk+1][lr]=vb.y; Bs[lk+2][lr]=vb.z; Bs[lk+3][lr]=vb.w;
        __syncthreads();
#pragma unroll
        for (int k = 0; k < 8; k++) {
            float a[8], b[8];
#pragma unroll
            for (int i = 0; i < 8; i++) a[i] = As[k][ty*8 + i];
#pragma unroll
            for (int j = 0; j < 8; j++) b[j] = Bs[k][tx*8 + j];
#pragma unroll
            for (int i = 0; i < 8; i++)
#pragma unroll
                for (int j = 0; j < 8; j++) acc[i][j] += a[i] * b[j];
        }
    }
#pragma unroll
    for (int i = 0; i < 8; i++) {
        int gm = m0 + ty*8 + i;
        if (gm >= M) continue;
#pragma unroll
        for (int j = 0; j < 8; j++) {
            int gn = n0 + tx*8 + j;
            if (gn >= N) continue;
            C[(size_t)gm * N + gn] = acc[i][j];
        }
    }
}

// ===================== tensor-core flash attention (split-bf16) =====================
// Block = (64 q rows, one b*h). 128 threads / 4 warps; warp owns 16 q rows.
// K-dim split: Q/P = [hi,hi,lo], K/V = [hi,lo,hi] -> 3-term exact products.
// smem: sK 64x384B (24KB) | sV 192x128B (24KB) | sP 64x384B (24KB, also Q staging)
#define ATT_SMEM 73728
__global__ void __launch_bounds__(128, 3)
attn_mma(const float* __restrict__ qkv, __nv_bfloat16* __restrict__ ctx2) {
    extern __shared__ char dsm[];
    char* cK = dsm;
    char* cV = dsm + 24576;
    char* cP = dsm + 49152;
    uint32_t sK = smem_u32(cK), sV = smem_u32(cV), sP = smem_u32(cP);

    int tid = threadIdx.x, wid = tid >> 5, lane = tid & 31;
    int q0 = blockIdx.x * 64;
    int bh = blockIdx.y;
    int b = bh / HEADS_, hh = bh - b*HEADS_;
    const float* base = qkv + (size_t)b * S_ * TRID_ + hh * HD_;

    // ---- stage Q (scaled 1/8) into sP: rows q (384B), segs: [hi|hi|lo] ----
#pragma unroll
    for (int i = 0; i < 4; i++) {
        int task = tid + 128*i;
        int r = task >> 3, dg = task & 7;
        int qg = q0 + r;
        float4 u0 = make_float4(0.f,0.f,0.f,0.f), u1 = u0;
        if (qg < S_) {
            const float* p = base + (size_t)qg * TRID_ + dg*8;
            u0 = *(const float4*)p; u1 = *(const float4*)(p + 4);
        }
        float v[8] = {u0.x,u0.y,u0.z,u0.w,u1.x,u1.y,u1.z,u1.w};
        uint32_t hi[4], lo[4];
#pragma unroll
        for (int j = 0; j < 4; j++) {
            __nv_bfloat16 h0,l0,h1,l1;
            split_bf(v[2*j]*0.125f, h0, l0);
            split_bf(v[2*j+1]*0.125f, h1, l1);
            hi[j] = pk2(h0, h1); lo[j] = pk2(l0, l1);
        }
        uint32_t ph = ((uint32_t)(dg ^ (r & 7))) << 4;
        uint32_t rb = (uint32_t)r * 384;
        *(uint4*)(cP + rb + ph)       = make_uint4(hi[0],hi[1],hi[2],hi[3]);
        *(uint4*)(cP + rb + 128 + ph) = make_uint4(hi[0],hi[1],hi[2],hi[3]);
        *(uint4*)(cP + rb + 256 + ph) = make_uint4(lo[0],lo[1],lo[2],lo[3]);
    }
    __syncthreads();

    // ---- Q fragments (register resident): 12 k-steps ----
    uint32_t qf[12][4];
#pragma unroll
    for (int ks = 0; ks < 12; ks++) {
        int row = wid*16 + (lane & 15);
        int kc = ks*2 + (lane >> 4);
        uint32_t addr = sP + row*384 +
            (((uint32_t)((kc & 24) | ((kc & 7) ^ (row & 7)))) << 4);
        ldsm4(qf[ks][0], qf[ks][1], qf[ks][2], qf[ks][3], addr);
    }

    float O[8][4];
#pragma unroll
    for (int g = 0; g < 8; g++)
#pragma unroll
        for (int e = 0; e < 4; e++) O[g][e] = 0.f;
    float m0r = -1e30f, m1r = -1e30f, l0r = 0.f, l1r = 0.f;

    for (int kt = 0; kt < 4; kt++) {
        __syncthreads();
        // ---- convert K, V tiles ----
#pragma unroll
        for (int i = 0; i < 4; i++) {
            int task = tid + 128*i;
            int r = task >> 3, dg = task & 7;
            int kg = kt*64 + r;
            float4 k0 = make_float4(0.f,0.f,0.f,0.f), k1 = k0, v0 = k0, v1 = k0;
            if (kg < S_) {
                const float* pk = base + D_   + (size_t)kg * TRID_ + dg*8;
                const float* pv = base + 2*D_ + (size_t)kg * TRID_ + dg*8;
                k0 = *(const float4*)pk; k1 = *(const float4*)(pk + 4);
                v0 = *(const float4*)pv; v1 = *(const float4*)(pv + 4);
            }
            uint32_t ph = ((uint32_t)(dg ^ (r & 7))) << 4;
            {
                float v[8] = {k0.x,k0.y,k0.z,k0.w,k1.x,k1.y,k1.z,k1.w};
                uint32_t hi[4], lo[4];
#pragma unroll
                for (int j = 0; j < 4; j++) {
                    __nv_bfloat16 h0,l0,h1,l1;
                    split_bf(v[2*j], h0, l0);
                    split_bf(v[2*j+1], h1, l1);
                    hi[j] = pk2(h0,h1); lo[j] = pk2(l0,l1);
                }
                uint32_t rb = (uint32_t)r * 384;
                *(uint4*)(cK + rb + ph)       = make_uint4(hi[0],hi[1],hi[2],hi[3]);
                *(uint4*)(cK + rb + 128 + ph) = make_uint4(lo[0],lo[1],lo[2],lo[3]);
                *(uint4*)(cK + rb + 256 + ph) = make_uint4(hi[0],hi[1],hi[2],hi[3]);
            }
            {
                float v[8] = {v0.x,v0.y,v0.z,v0.w,v1.x,v1.y,v1.z,v1.w};
                uint32_t hi[4], lo[4];
#pragma unroll
                for (int j = 0; j < 4; j++) {
                    __nv_bfloat16 h0,l0,h1,l1;
                    split_bf(v[2*j], h0, l0);
                    split_bf(v[2*j+1], h1, l1);
                    hi[j] = pk2(h0,h1); lo[j] = pk2(l0,l1);
                }
                *(uint4*)(cV + (uint32_t)r*128 + ph)        = make_uint4(hi[0],hi[1],hi[2],hi[3]);
                *(uint4*)(cV + (uint32_t)(64 + r)*128 + ph)  = make_uint4(lo[0],lo[1],lo[2],lo[3]);
                *(uint4*)(cV + (uint32_t)(128 + r)*128 + ph) = make_uint4(hi[0],hi[1],hi[2],hi[3]);
            }
        }
        __syncthreads();

        // ---- S = Q2 @ K2^T ----
        float sacc[8][4];
#pragma unroll
        for (int g = 0; g < 8; g++)
#pragma unroll
            for (int e = 0; e < 4; e++) sacc[g][e] = 0.f;
#pragma unroll
        for (int ks = 0; ks < 12; ks++) {
            uint32_t bf[4][4];
#pragma unroll
            for (int g2 = 0; g2 < 4; g2++) {
                int nr = g2*16 + ((lane >> 4) << 3) + (lane & 7);
                int kc = ks*2 + ((lane >> 3) & 1);
                uint32_t addr = sK + nr*384 +
                    (((uint32_t)((kc & 24) | ((kc & 7) ^ (nr & 7)))) << 4);
                ldsm4(bf[g2][0], bf[g2][1], bf[g2][2], bf[g2][3], addr);
            }
#pragma unroll
            for (int g = 0; g < 8; g++)
                mma16816(sacc[g], qf[ks][0], qf[ks][1], qf[ks][2], qf[ks][3],
                         bf[g >> 1][(g & 1)*2], bf[g >> 1][(g & 1)*2 + 1]);
        }

        // ---- mask + online softmax ----
        int cb = (lane & 3)*2;
#pragma unroll
        for (int g = 0; g < 8; g++) {
            int col = kt*64 + g*8 + cb;
            if (col >= S_)     { sacc[g][0] = -1e30f; sacc[g][2] = -1e30f; }
            if (col + 1 >= S_) { sacc[g][1] = -1e30f; sacc[g][3] = -1e30f; }
        }
        float mt0 = -1e30f, mt1 = -1e30f;
#pragma unroll
        for (int g = 0; g < 8; g++) {
            mt0 = fmaxf(mt0, fmaxf(sacc[g][0], sacc[g][1]));
            mt1 = fmaxf(mt1, fmaxf(sacc[g][2], sacc[g][3]));
        }
        mt0 = fmaxf(mt0, __shfl_xor_sync(0xffffffffu, mt0, 1));
        mt0 = fmaxf(mt0, __shfl_xor_sync(0xffffffffu, mt0, 2));
        mt1 = fmaxf(mt1, __shfl_xor_sync(0xffffffffu, mt1, 1));
        mt1 = fmaxf(mt1, __shfl_xor_sync(0xffffffffu, mt1, 2));
        float mn0 = fmaxf(m0r, mt0), mn1 = fmaxf(m1r, mt1);
        float r0 = __expf(m0r - mn0), r1 = __expf(m1r - mn1);
        float ls0 = 0.f, ls1 = 0.f;
#pragma unroll
        for (int g = 0; g < 8; g++) {
            sacc[g][0] = __expf(sacc[g][0] - mn0);
            sacc[g][1] = __expf(sacc[g][1] - mn0);
            sacc[g][2] = __expf(sacc[g][2] - mn1);
            sacc[g][3] = __expf(sacc[g][3] - mn1);
            ls0 += sacc[g][0] + sacc[g][1];
            ls1 += sacc[g][2] + sacc[g][3];
        }
        ls0 += __shfl_xor_sync(0xffffffffu, ls0, 1);
        ls0 += __shfl_xor_sync(0xffffffffu, ls0, 2);
        ls1 += __shfl_xor_sync(0xffffffffu, ls1, 1);
        ls1 += __shfl_xor_sync(0xffffffffu, ls1, 2);
        l0r = l0r * r0 + ls0;
        l1r = l1r * r1 + ls1;
        m0r = mn0; m1r = mn1;
#pragma unroll
        for (int g = 0; g < 8; g++) {
            O[g][0] *= r0; O[g][1] *= r0;
            O[g][2] *= r1; O[g][3] *= r1;
        }

        // ---- write P2 split (own warp rows only) ----
        int pr0 = wid*16 + (lane >> 2), pr1 = pr0 + 8;
#pragma unroll
        for (int g = 0; g < 8; g++) {
            __nv_bfloat16 h0,l0,h1,l1;
            split_bf(sacc[g][0], h0, l0); split_bf(sacc[g][1], h1, l1);
            uint32_t hi2 = pk2(h0,h1), lo2 = pk2(l0,l1);
            uint32_t ph = (((uint32_t)(g ^ (pr0 & 7))) << 4) + (lane & 3)*4;
            *(uint32_t*)(cP + pr0*384 + ph)       = hi2;
            *(uint32_t*)(cP + pr0*384 + 128 + ph) = hi2;
            *(uint32_t*)(cP + pr0*384 + 256 + ph) = lo2;
            split_bf(sacc[g][2], h0, l0); split_bf(sacc[g][3], h1, l1);
            hi2 = pk2(h0,h1); lo2 = pk2(l0,l1);
            uint32_t ph1 = (((uint32_t)(g ^ (pr1 & 7))) << 4) + (lane & 3)*4;
            *(uint32_t*)(cP + pr1*384 + ph1)       = hi2;
            *(uint32_t*)(cP + pr1*384 + 128 + ph1) = hi2;
            *(uint32_t*)(cP + pr1*384 + 256 + ph1) = lo2;
        }
        __syncwarp();

        // ---- O += P2 @ V2 ----
#pragma unroll
        for (int ks = 0; ks < 12; ks++) {
            uint32_t af[4];
            {
                int row = wid*16 + (lane & 15);
                int kc = ks*2 + (lane >> 4);
                uint32_t addr = sP + row*384 +
                    (((uint32_t)((kc & 24) | ((kc & 7) ^ (row & 7)))) << 4);
                ldsm4(af[0], af[1], af[2], af[3], addr);
            }
            uint32_t vb[4][4];
#pragma unroll
            for (int g2 = 0; g2 < 4; g2++) {
                int vr = ks*16 + ((lane >> 3) & 1)*8 + (lane & 7);
                int seg = g2*2 + (lane >> 4);
                uint32_t addr = sV + vr*128 + (((uint32_t)(seg ^ (vr & 7))) << 4);
                ldsm4t(vb[g2][0], vb[g2][1], vb[g2][2], vb[g2][3], addr);
            }
#pragma unroll
            for (int g = 0; g < 8; g++)
                mma16816(O[g], af[0], af[1], af[2], af[3],
                         vb[g >> 1][(g & 1)*2], vb[g >> 1][(g & 1)*2 + 1]);
        }
    }

    // ---- epilogue: O /= l, split-write to ctx2 ----
    int r0g = q0 + wid*16 + (lane >> 2);
    int r1g = r0g + 8;
    float inv0 = 1.f / l0r, inv1 = 1.f / l1r;
#pragma unroll
    for (int g = 0; g < 8; g++) {
        int d = hh*HD_ + g*8 + (lane & 3)*2;
        if (r0g < S_) {
            __nv_bfloat16 h0,l0,h1,l1;
            split_bf(O[g][0]*inv0, h0, l0); split_bf(O[g][1]*inv0, h1, l1);
            uint32_t hi2 = pk2(h0,h1), lo2 = pk2(l0,l1);
            size_t rb = (size_t)(b*S_ + r0g) * TRID_ + d;
            *(uint32_t*)(ctx2 + rb)        = hi2;
            *(uint32_t*)(ctx2 + rb + D_)   = hi2;
            *(uint32_t*)(ctx2 + rb + 2*D_) = lo2;
        }
        if (r1g < S_) {
            __nv_bfloat16 h0,l0,h1,l1;
            split_bf(O[g][2]*inv1, h0, l0); split_bf(O[g][3]*inv1, h1, l1);
            uint32_t hi2 = pk2(h0,h1), lo2 = pk2(l0,l1);
            size_t rb = (size_t)(b*S_ + r1g) * TRID_ + d;
            *(uint32_t*)(ctx2 + rb)        = hi2;
            *(uint32_t*)(ctx2 + rb + D_)   = hi2;
            *(uint32_t*)(ctx2 + rb + 2*D_) = lo2;
        }
    }
}

// ===================== launch =====================
extern "C" void kernel_launch(void* const* d_in, const int* in_sizes, int n_in,
                              void* d_out, int out_size) {
    const float* x         = (const float*)d_in[0];
    const float* patch_w   = (const float*)d_in[1];
    const float* patch_b   = (const float*)d_in[2];
    const float* cls_token = (const float*)d_in[3];
    const float* pos_embed = (const float*)d_in[4];
    const float* ln1_g     = (const float*)d_in[5];
    const float* ln1_b     = (const float*)d_in[6];
    const float* qkv_w     = (const float*)d_in[7];
    const float* qkv_b     = (const float*)d_in[8];
    const float* out_w     = (const float*)d_in[9];
    const float* out_b     = (const float*)d_in[10];
    const float* ln2_g     = (const float*)d_in[11];
    const float* ln2_b     = (const float*)d_in[12];
    const float* fc1_w     = (const float*)d_in[13];
    const float* fc1_b     = (const float*)d_in[14];
    const float* fc2_w     = (const float*)d_in[15];
    const float* fc2_b     = (const float*)d_in[16];
    const float* lnf_g     = (const float*)d_in[17];
    const float* lnf_b     = (const float*)d_in[18];
    const float* head_w    = (const float*)d_in[19];
    float* out = (float*)d_out;

    float *h, *tok, *qkv, *cls;
    __nv_bfloat16 *x2, *ctx2, *hid2, *p2, *pw2, *qkvw2, *outw2, *fc1w2, *fc2w2;
    cudaGetSymbolAddress((void**)&h,     g_h);
    cudaGetSymbolAddress((void**)&tok,   g_tok);
    cudaGetSymbolAddress((void**)&qkv,   g_qkv);
    cudaGetSymbolAddress((void**)&cls,   g_cls);
    cudaGetSymbolAddress((void**)&x2,    g_x2);
    cudaGetSymbolAddress((void**)&ctx2,  g_ctx2);
    cudaGetSymbolAddress((void**)&hid2,  g_hid2);
    cudaGetSymbolAddress((void**)&p2,    g_p2);
    cudaGetSymbolAddress((void**)&pw2,   g_pw2);
    cudaGetSymbolAddress((void**)&qkvw2, g_qkvw2);
    cudaGetSymbolAddress((void**)&outw2, g_outw2);
    cudaGetSymbolAddress((void**)&fc1w2, g_fc1w2);
    cudaGetSymbolAddress((void**)&fc2w2, g_fc2w2);

    cudaFuncSetAttribute(gemm_mma<0>, cudaFuncAttributeMaxDynamicSharedMemorySize, GMM_SMEM);
    cudaFuncSetAttribute(gemm_mma<1>, cudaFuncAttributeMaxDynamicSharedMemorySize, GMM_SMEM);
    cudaFuncSetAttribute(gemm_mma<2>, cudaFuncAttributeMaxDynamicSharedMemorySize, GMM_SMEM);
    cudaFuncSetAttribute(attn_mma,    cudaFuncAttributeMaxDynamicSharedMemorySize, ATT_SMEM);

    auto wlaunch = [](const float* src, __nv_bfloat16* dst, int R, int K) {
        size_t n = (size_t)R * K;
        wsplit_k<<<(unsigned)((n + 255) / 256), 256>>>(src, dst, R, K);
    };

    // Launch order: user launch #4 is attn_mma (dummy pass on scratch g_qkv; its
    // output ctx2 is fully overwritten before first use). ncu -s 5 -c 1 captures it.
    wlaunch(patch_w, pw2, D_, PD_);                                        // 1
    patchify_k<<<(unsigned)(((size_t)BT_*PD_ + 255) / 256), 256>>>(x, p2); // 2
    wlaunch(qkv_w, qkvw2, DEPTH_*TRID_, D_);                               // 3
    attn_mma<<<dim3(4, B_*HEADS_), 128, ATT_SMEM>>>(qkv, ctx2);            // 4 <- profiled
    gemm_mma<0><<<dim3(D_/128, BT_/128), 256, GMM_SMEM>>>(p2, pw2, patch_b, nullptr,
                                                          tok, BT_, D_, 3*PD_);
    wlaunch(out_w, outw2, DEPTH_*D_, D_);
    wlaunch(fc1_w, fc1w2, DEPTH_*HID_, D_);
    wlaunch(fc2_w, fc2w2, DEPTH_*D_, HID_);
    assemble_k<<<(T_*D_ + 255)/256, 256>>>(tok, cls_token, pos_embed, h);

    const int lnBlocks = (T_ + 7) / 8;
    for (int L = 0; L < DEPTH_; L++) {
        ln_k<1><<<lnBlocks, 256>>>(h, nullptr, x2, ln1_g + L*D_, ln1_b + L*D_, T_, D_);
        gemm_mma<0><<<dim3(TRID_/128, T_/128), 256, GMM_SMEM>>>(
            x2, qkvw2 + (size_t)L*TRID_*3*D_, qkv_b + L*TRID_, nullptr,
            qkv, T_, TRID_, 3*D_);
        attn_mma<<<dim3(4, B_*HEADS_), 128, ATT_SMEM>>>(qkv, ctx2);
        gemm_mma<1><<<dim3(D_/128, T_/128), 256, GMM_SMEM>>>(
            ctx2, outw2 + (size_t)L*D_*3*D_, out_b + L*D_, h,
            h, T_, D_, 3*D_);
        ln_k<1><<<lnBlocks, 256>>>(h, nullptr, x2, ln2_g + L*D_, ln2_b + L*D_, T_, D_);
        gemm_mma<2><<<dim3(HID_/128, T_/128), 256, GMM_SMEM>>>(
            x2, fc1w2 + (size_t)L*HID_*3*D_, fc1_b + L*HID_, nullptr,
            hid2, T_, HID_, 3*D_);
        gemm_mma<1><<<dim3(D_/128, T_/128), 256, GMM_SMEM>>>(
            hid2, fc2w2 + (size_t)L*D_*3*HID_, fc2_b + L*D_, h,
            h, T_, D_, 3*HID_);
    }

    ln_k<0><<<(B_ + 7)/8, 256>>>(h, cls, nullptr, lnf_g, lnf_b, B_, S_*D_);
    gemm32_k<<<dim3(1, 1), 256>>>(cls, head_w, out, B_, NCLS_, D_);
}